// round 11
// baseline (speedup 1.0000x reference)
#include <cuda_runtime.h>
#include <cuda_bf16.h>
#include <math.h>

// NIQE-style patch statistics + Mahalanobis distance. SINGLE fused kernel.
// x: (8,4,1056,1056) fp32. PATCH=96, STRIDE=48 -> 21x21 patches per image.
//
// Stage 1 (all 1408 blocks): per (image, 24-row strip) segment sums
//   (X, X2, gx^2, gy^2, Hlast, bndG) -> g_seg.
// Stage 2 (last block of each image's 44, via per-image atomic counter):
//   compute that image's 441 patch stats from g_seg, shuffle-reduce ->
//   g_feat[bc]. Overlaps with stage-1 blocks of other images.
// Stage 3 (last image to finish, via global counter): single-warp
//   Gauss-Jordan solve cov[:12,:12] * Y = D, Mahalanobis, mean -> out.
// All counters self-reset for CUDA-graph replay; cross-SM data read via ldcg.

#define IMW 1056
#define NSTRIP 44   // 1056 / 24
#define SROWS 24
#define NPR 21
#define NBC 32
#define P1_T 288
#define NF4 264     // 1056/4 float4-columns
#define NSEG 22     // 1056/48 segments
#define SEGSTR (6 * NSEG)   // per (bc,strip): X,X2,G,H,Hl,bndG
#define FULLM 0xffffffffu

__device__ float g_seg [NBC * NSTRIP * SEGSTR];
__device__ float g_feat[NBC * 3];
__device__ unsigned int g_img_ctr[NBC];   // zero-initialized
__device__ unsigned int g_ctr = 0;

__global__ __launch_bounds__(P1_T, 4)
void niqe_fused(const float* __restrict__ x,
                const float* __restrict__ mu_p,
                const float* __restrict__ cov_p,
                float* __restrict__ out) {
    const int s   = blockIdx.x;   // strip 0..43
    const int bc  = blockIdx.y;   // image 0..31
    const int tid = threadIdx.x;
    const int wid  = tid >> 5;
    const int lane = tid & 31;

    __shared__ float red[5][NF4];
    __shared__ float bnd[NSEG];

    // ================= stage 1: strip segment sums =================
    {
        float aX = 0.f, aS = 0.f, aG = 0.f, aG3 = 0.f, aH = 0.f, hl = 0.f;

        if (tid < NF4) {
            const int j0   = tid * 4;
            const int offn = (tid < NF4 - 1) ? 4 : 3;  // clamp: edge d3 = 0 exactly
            const float* img = x + (size_t)bc * IMW * IMW + (size_t)s * SROWS * IMW;
            float pv0, pv1, pv2, pv3;

            // row 0: x-stats + gx (no gy)
            {
                const float4 v = *(const float4*)(img + j0);
                const float vn = img[j0 + offn];
                aX += v.x + v.y + v.z + v.w;
                aS += v.x*v.x + v.y*v.y + v.z*v.z + v.w*v.w;
                float d0 = v.y - v.x, d1 = v.z - v.y, d2 = v.w - v.z, d3 = vn - v.w;
                aG  += d0*d0 + d1*d1 + d2*d2;
                aG3 += d3*d3;
                pv0 = v.x; pv1 = v.y; pv2 = v.z; pv3 = v.w;
            }
            // rows 1..23
            #pragma unroll 8
            for (int i = 1; i < SROWS; ++i) {
                const float* rp = img + (size_t)i * IMW;
                const float4 v = *(const float4*)(rp + j0);
                const float vn = rp[j0 + offn];
                aX += v.x + v.y + v.z + v.w;
                aS += v.x*v.x + v.y*v.y + v.z*v.z + v.w*v.w;
                float e0 = v.x - pv0, e1 = v.y - pv1, e2 = v.z - pv2, e3 = v.w - pv3;
                aH += e0*e0 + e1*e1 + e2*e2 + e3*e3;
                float d0 = v.y - v.x, d1 = v.z - v.y, d2 = v.w - v.z, d3 = vn - v.w;
                aG  += d0*d0 + d1*d1 + d2*d2;
                aG3 += d3*d3;
                pv0 = v.x; pv1 = v.y; pv2 = v.z; pv3 = v.w;
            }
            // overlap row (first row of next strip): gy only -> also Hlast
            if (s != NSTRIP - 1) {
                const float* rp = img + (size_t)SROWS * IMW;
                const float4 v = *(const float4*)(rp + j0);
                float e0 = v.x - pv0, e1 = v.y - pv1, e2 = v.z - pv2, e3 = v.w - pv3;
                hl  = e0*e0 + e1*e1 + e2*e2 + e3*e3;
                aH += hl;
            }

            red[0][tid] = aX;
            red[1][tid] = aS;
            red[2][tid] = aG + aG3;
            red[3][tid] = aH;
            red[4][tid] = hl;
            if ((tid % 12) == 11) bnd[tid / 12] = aG3;  // colG at column 48m+47
        }
        __syncthreads();

        float* outp = g_seg + ((size_t)bc * NSTRIP + s) * SEGSTR;
        if (tid < 5 * NSEG) {
            const int stat = tid / NSEG, m = tid % NSEG;
            float acc = 0.f;
            #pragma unroll
            for (int q = 0; q < 12; ++q) acc += red[stat][12 * m + q];
            outp[stat * NSEG + m] = acc;
        } else if (tid < 6 * NSEG) {
            outp[tid] = bnd[tid - 5 * NSEG];   // stat 5 = bndG
        }
    }

    // ============ per-image completion: last of 44 runs stage 2 ============
    __shared__ unsigned int fImg;
    __threadfence();
    __syncthreads();
    if (tid == 0) fImg = (atomicAdd(&g_img_ctr[bc], 1u) == NSTRIP - 1) ? 1u : 0u;
    __syncthreads();
    if (!fImg) return;
    if (tid == 0) g_img_ctr[bc] = 0;   // reset for next graph replay

    // ================= stage 2: patch stats for image bc =================
    {
        __shared__ float w0[9], w1[9], w2[9];
        float mu = 0.f, var = 0.f, gm = 0.f;
        for (int p = tid; p < NPR * NPR; p += P1_T) {
            const int pr = p / NPR, pc = p % NPR;
            const float* base = g_seg + ((size_t)bc * NSTRIP + 2 * pr) * SEGSTR;
            float X = 0.f, S = 0.f, G = 0.f, H = 0.f;
            #pragma unroll
            for (int s4 = 0; s4 < 4; ++s4) {
                const float* seg = base + s4 * SEGSTR;
                X += __ldcg(seg + 0*NSEG + pc) + __ldcg(seg + 0*NSEG + pc + 1);
                S += __ldcg(seg + 1*NSEG + pc) + __ldcg(seg + 1*NSEG + pc + 1);
                G += __ldcg(seg + 2*NSEG + pc) + __ldcg(seg + 2*NSEG + pc + 1)
                   - __ldcg(seg + 5*NSEG + pc + 1);
                H += __ldcg(seg + 3*NSEG + pc) + __ldcg(seg + 3*NSEG + pc + 1);
            }
            const float* seg3 = base + 3 * SEGSTR;
            H -= __ldcg(seg3 + 4*NSEG + pc) + __ldcg(seg3 + 4*NSEG + pc + 1);
            mu  += X / 9216.0f;
            var += (S - X * X / 9216.0f) / 9215.0f;
            gm  += sqrtf((G + H) / 9120.0f);
        }
        #pragma unroll
        for (int off = 16; off; off >>= 1) {
            mu  += __shfl_xor_sync(FULLM, mu,  off);
            var += __shfl_xor_sync(FULLM, var, off);
            gm  += __shfl_xor_sync(FULLM, gm,  off);
        }
        if (lane == 0) { w0[wid] = mu; w1[wid] = var; w2[wid] = gm; }
        __syncthreads();
        if (wid == 0) {
            float a = (lane < 9) ? w0[lane] : 0.f;
            float b = (lane < 9) ? w1[lane] : 0.f;
            float c = (lane < 9) ? w2[lane] : 0.f;
            #pragma unroll
            for (int off = 8; off; off >>= 1) {
                a += __shfl_xor_sync(FULLM, a, off, 16);
                b += __shfl_xor_sync(FULLM, b, off, 16);
                c += __shfl_xor_sync(FULLM, c, off, 16);
            }
            if (lane == 0) {
                g_feat[bc * 3 + 0] = a;
                g_feat[bc * 3 + 1] = b;
                g_feat[bc * 3 + 2] = c;
            }
        }
    }

    // ============ global completion: last image runs stage 3 ============
    __shared__ unsigned int fAll;
    __threadfence();
    __syncthreads();
    if (tid == 0) fAll = (atomicAdd(&g_ctr, 1u) == NBC - 1) ? 1u : 0u;
    __syncthreads();
    if (!fAll) return;
    if (tid == 0) g_ctr = 0;   // reset for next graph replay
    if (wid != 0) return;

    // lane i (i<12) owns row i of [ cov(12x12) | D(12x8) ],
    // D[:,b] = feats[b] - mu_pristine. feats fi = s*4 + c; bc = b*4 + c.
    float a[12], r[8], d0[8];
    const int i = lane;
    if (i < 12) {
        #pragma unroll
        for (int j = 0; j < 12; ++j) a[j] = cov_p[i * 36 + j];
        const int st = i >> 2, c = i & 3;
        #pragma unroll
        for (int b = 0; b < 8; ++b) {
            float f = __ldcg(&g_feat[(b * 4 + c) * 3 + st]) / 441.0f;
            d0[b] = f - mu_p[i];
            r[b]  = d0[b];
        }
    } else {
        #pragma unroll
        for (int j = 0; j < 12; ++j) a[j] = 0.f;
        #pragma unroll
        for (int b = 0; b < 8; ++b) { r[b] = 0.f; d0[b] = 0.f; }
    }

    // Gauss-Jordan elimination (no row scaling): after 12 iterations row i
    // holds only its diagonal in A, so Y[i][b] = r[b] / a[i].
    #pragma unroll
    for (int k = 0; k < 12; ++k) {
        const float akk = __shfl_sync(FULLM, a[k], k);
        float f = a[k] / akk;
        if (i == k || i >= 12) f = 0.f;
        #pragma unroll
        for (int j = 0; j < 12; ++j) a[j] -= f * __shfl_sync(FULLM, a[j], k);
        #pragma unroll
        for (int b = 0; b < 8; ++b)  r[b] -= f * __shfl_sync(FULLM, r[b], k);
    }

    // q_b = sum_i d0[i][b] * y[i][b]  (lanes >= 12 contribute 0)
    const float invd = (i < 12) ? (1.0f / a[i]) : 0.f;
    float ssum = 0.f;
    #pragma unroll
    for (int b = 0; b < 8; ++b) {
        float t = d0[b] * r[b] * invd;
        #pragma unroll
        for (int off = 16; off; off >>= 1)
            t += __shfl_xor_sync(FULLM, t, off);
        if (lane == 0) ssum += sqrtf(t);
    }
    if (lane == 0) out[0] = ssum * 0.125f;
}

extern "C" void kernel_launch(void* const* d_in, const int* in_sizes, int n_in,
                              void* d_out, int out_size) {
    const float* x     = (const float*)d_in[0];
    const float* mu_p  = (const float*)d_in[1];
    const float* cov_p = (const float*)d_in[2];
    float* out = (float*)d_out;

    niqe_fused<<<dim3(NSTRIP, NBC), P1_T>>>(x, mu_p, cov_p, out);
}